// round 15
// baseline (speedup 1.0000x reference)
#include <cuda_runtime.h>
#include <cuda_fp16.h>
#include <math.h>
#include <stdint.h>

// Shapes (fixed)
#define NB    2
#define NN    256
#define NK    16
#define ND    64
#define NHID  128
#define NKVD  256
#define NODES 512
#define EDGES 8192
#define KAUG  4160          // 64*64 + 64 bias rows

// ---------------- scratch ----------------
__device__ float g_q[NODES*NHID];
__device__ float g_xi[NODES*ND];
__device__ float g_xj[NODES*ND];
__device__ float g_hdd[EDGES*64];
__device__ __align__(128) __half g_wt[NKVD*KAUG];   // [o2][kaug], fp16
__device__ float g_maskf[EDGES];

__device__ __forceinline__ float silu(float x){ return x / (1.f + __expf(-x)); }

// ---------------- fused pre (prenorm+proj) + radial MLP + mask detect ----------------
// grid: [0,512) radial (16 edges each), [512, 512+NODES) pre, 512+NODES mask
__global__ void __launch_bounds__(256) k_pre_radial(
    const float* __restrict__ f, const float* __restrict__ nscale,
    const float* __restrict__ Wq, const float* __restrict__ Wxi,
    const float* __restrict__ Wxj, const unsigned char* __restrict__ mraw,
    const float* __restrict__ rel,
    const float* __restrict__ W1, const float* __restrict__ b1,
    const float* __restrict__ g1, const float* __restrict__ W2,
    const float* __restrict__ b2, const float* __restrict__ g2){
  int t = threadIdx.x;

  if (blockIdx.x < 512){
    // ---- radial: warp handles 2 edges, interleaved phases ----
    __shared__ float sW2[64][64];
    __shared__ float shh[16][64];
    int w = t >> 5, lane = t & 31;
    #pragma unroll
    for (int i = 0; i < 4; i++)
      ((float4*)sW2)[t + i*256] = ((const float4*)W2)[t + i*256];
    __syncthreads();
    int c0 = lane, c1 = lane + 32;
    float w1c0 = W1[c0], w1c1 = W1[c1];
    float b1c0 = b1[c0], b1c1 = b1[c1];
    float g1c0 = g1[c0], g1c1 = g1[c1];
    float b2c0 = b2[c0], b2c1 = b2[c1];
    float g2c0 = g2[c0], g2c1 = g2[c1];

    int sl0 = w*2, sl1 = sl0 + 1;
    int e0  = blockIdx.x*16 + sl0, e1 = e0 + 1;
    float r0 = rel[e0], r1 = rel[e1];

    // phase 1: both edges, interleaved
    float h00 = silu(fmaf(r0, w1c0, b1c0));
    float h01 = silu(fmaf(r0, w1c1, b1c1));
    float h10 = silu(fmaf(r1, w1c0, b1c0));
    float h11 = silu(fmaf(r1, w1c1, b1c1));
    float s0 = h00 + h01, q0 = h00*h00 + h01*h01;
    float s1 = h10 + h11, q1 = h10*h10 + h11*h11;
    #pragma unroll
    for (int o = 16; o; o >>= 1){
      s0 += __shfl_xor_sync(0xffffffffu, s0, o);
      q0 += __shfl_xor_sync(0xffffffffu, q0, o);
      s1 += __shfl_xor_sync(0xffffffffu, s1, o);
      q1 += __shfl_xor_sync(0xffffffffu, q1, o);
    }
    float mu0 = s0*(1.f/64.f), rs0 = rsqrtf(q0*(1.f/64.f) - mu0*mu0 + 1e-5f);
    float mu1 = s1*(1.f/64.f), rs1 = rsqrtf(q1*(1.f/64.f) - mu1*mu1 + 1e-5f);
    h00 = (h00 - mu0)*rs0*g1c0;  h01 = (h01 - mu0)*rs0*g1c1;
    h10 = (h10 - mu1)*rs1*g1c0;  h11 = (h11 - mu1)*rs1*g1c1;
    shh[sl0][c0] = h00;  shh[sl0][c1] = h01;
    shh[sl1][c0] = h10;  shh[sl1][c1] = h11;
    __syncwarp();

    // phase 2 matvec: both edges share W2 loads, 4 accumulators
    float a00 = b2c0, a01 = b2c1, a10 = b2c0, a11 = b2c1;
    #pragma unroll
    for (int i = 0; i < 64; i++){
      float wv0 = sW2[i][c0], wv1 = sW2[i][c1];
      float hv0 = shh[sl0][i], hv1 = shh[sl1][i];
      a00 = fmaf(hv0, wv0, a00);
      a01 = fmaf(hv0, wv1, a01);
      a10 = fmaf(hv1, wv0, a10);
      a11 = fmaf(hv1, wv1, a11);
    }
    a00 = silu(a00); a01 = silu(a01); a10 = silu(a10); a11 = silu(a11);
    s0 = a00 + a01; q0 = a00*a00 + a01*a01;
    s1 = a10 + a11; q1 = a10*a10 + a11*a11;
    #pragma unroll
    for (int o = 16; o; o >>= 1){
      s0 += __shfl_xor_sync(0xffffffffu, s0, o);
      q0 += __shfl_xor_sync(0xffffffffu, q0, o);
      s1 += __shfl_xor_sync(0xffffffffu, s1, o);
      q1 += __shfl_xor_sync(0xffffffffu, q1, o);
    }
    mu0 = s0*(1.f/64.f); rs0 = rsqrtf(q0*(1.f/64.f) - mu0*mu0 + 1e-5f);
    mu1 = s1*(1.f/64.f); rs1 = rsqrtf(q1*(1.f/64.f) - mu1*mu1 + 1e-5f);
    g_hdd[e0*64 + c0] = (a00 - mu0)*rs0*g2c0;
    g_hdd[e0*64 + c1] = (a01 - mu0)*rs0*g2c1;
    g_hdd[e1*64 + c0] = (a10 - mu1)*rs1*g2c0;
    g_hdd[e1*64 + c1] = (a11 - mu1)*rs1*g2c1;
    return;
  }

  if (blockIdx.x == 512 + NODES){
    // ---- mask dtype detection + expansion ----
    __shared__ int flags[2];
    if (t < 2) flags[t] = 0;
    __syncthreads();
    int f3 = 0, fn = 0;
    for (int i = t; i < EDGES; i += 256){
      unsigned char bb = mraw[i];
      if (bb == 0x3fu) f3 = 1;
      if ((i & 3) && bb) fn = 1;
    }
    if (f3) atomicOr(&flags[0], 1);
    if (fn) atomicOr(&flags[1], 1);
    __syncthreads();
    int mode = flags[0] ? 2 : (flags[1] ? 0 : 1);
    for (int i = t; i < EDGES; i += 256){
      float m;
      if (mode == 2)      m = (((const float*)mraw)[i] != 0.f) ? 1.f : 0.f;
      else if (mode == 1) m = (((const int*)  mraw)[i] != 0  ) ? 1.f : 0.f;
      else                m = (mraw[i] != 0) ? 1.f : 0.f;
      g_maskf[i] = m;
    }
    return;
  }

  // ---- pre: prenorm + projections ----
  __shared__ float sv[ND];
  __shared__ float sx[ND];
  int node = blockIdx.x - 512;
  if (t < ND) sv[t] = f[node*ND + t];
  __syncthreads();
  float ss = 0.f;
  #pragma unroll
  for (int d = 0; d < ND; d++) ss = fmaf(sv[d], sv[d], ss);
  float den = fmaxf(sqrtf(ss) * 0.125f, 1e-12f);
  if (t < ND) sx[t] = sv[t] / den * nscale[t];
  __syncthreads();
  if (t < NHID){
    float a = 0.f;
    #pragma unroll
    for (int d = 0; d < ND; d++) a = fmaf(sx[d], Wq[d*NHID + t], a);
    g_q[node*NHID + t] = a;
  } else if (t < NHID + ND){
    int c = t - NHID; float a = 0.f;
    #pragma unroll
    for (int d = 0; d < ND; d++) a = fmaf(sx[d], Wxi[d*ND + c], a);
    g_xi[node*ND + c] = a;
  } else {
    int c = t - NHID - ND; float a = 0.f;
    #pragma unroll
    for (int d = 0; d < ND; d++) a = fmaf(sx[d], Wxj[d*ND + c], a);
    g_xj[node*ND + c] = a;
  }
}

// ---------------- shared MMA helpers ----------------
static __device__ __forceinline__ void cpasync16(unsigned sm, const void* g){
  asm volatile("cp.async.cg.shared.global [%0], [%1], 16;" :: "r"(sm), "l"(g));
}
static __device__ __forceinline__ void ldsm4(unsigned* r, unsigned addr){
  asm volatile("ldmatrix.sync.aligned.m8n8.x4.shared.b16 {%0,%1,%2,%3}, [%4];"
               : "=r"(r[0]), "=r"(r[1]), "=r"(r[2]), "=r"(r[3]) : "r"(addr));
}
static __device__ __forceinline__ void mma16816(float* c, const unsigned* a, const unsigned* b){
  asm volatile(
    "mma.sync.aligned.m16n8k16.row.col.f32.f16.f16.f32 "
    "{%0,%1,%2,%3}, {%4,%5,%6,%7}, {%8,%9}, {%0,%1,%2,%3};"
    : "+f"(c[0]), "+f"(c[1]), "+f"(c[2]), "+f"(c[3])
    : "r"(a[0]), "r"(a[1]), "r"(a[2]), "r"(a[3]), "r"(b[0]), "r"(b[1]));
}

// ================= wcomb via mma.sync (A hi/lo split, B hi only: 2 products) =================
#define W_STR 264
#define W_AHI 0
#define W_ALO 67584
#define W_BHI 135168
#define W_SMT 168960

__global__ void __launch_bounds__(256, 1) k_wcomb(
    const float* __restrict__ W3, const float* __restrict__ b3,
    const float* __restrict__ Wkv){
  extern __shared__ __align__(16) char smem[];
  const unsigned sbase = (unsigned)__cvta_generic_to_shared(smem);
  const int tid  = threadIdx.x;
  const int lane = tid & 31;
  const int wid  = tid >> 5;
  const int wm   = wid & 3;
  const int wn   = wid >> 2;
  const int r    = blockIdx.x;      // 0..64 (64 = bias block)
  const int n0   = blockIdx.y * 128;
  const float* srcB = (r < 64) ? (W3 + (size_t)r*16384) : b3;

  #pragma unroll
  for (int i = 0; i < 16; i++){
    int u = tid + i*256;
    int opair = u >> 5, f4 = u & 31;
    int o = opair*2, n = f4*4;
    float4 v0 = *(const float4*)(Wkv + (size_t)o*256 + n0 + n);
    float4 v1 = *(const float4*)(Wkv + (size_t)(o+1)*256 + n0 + n);
    const float* p0 = (const float*)&v0;
    const float* p1 = (const float*)&v1;
    #pragma unroll
    for (int j = 0; j < 4; j++){
      float x0 = p0[j], x1 = p1[j];
      __half h0 = __float2half_rn(x0), h1 = __float2half_rn(x1);
      __half l0 = __float2half_rn(x0 - __half2float(h0));
      __half l1 = __float2half_rn(x1 - __half2float(h1));
      __half2 hh; hh.x = h0; hh.y = h1;
      __half2 ll; ll.x = l0; ll.y = l1;
      unsigned off = (unsigned)((n + j)*W_STR + o)*2;
      *(__half2*)(smem + W_AHI + off) = hh;
      *(__half2*)(smem + W_ALO + off) = ll;
    }
  }
  #pragma unroll
  for (int i = 0; i < 8; i++){
    int u = tid + i*256;
    int opair = u >> 4, f4 = u & 15;
    int o = opair*2, d = f4*4;
    float4 v0 = *(const float4*)(srcB + (size_t)o*64 + d);
    float4 v1 = *(const float4*)(srcB + (size_t)(o+1)*64 + d);
    const float* p0 = (const float*)&v0;
    const float* p1 = (const float*)&v1;
    #pragma unroll
    for (int j = 0; j < 4; j++){
      __half2 hh = __floats2half2_rn(p0[j], p1[j]);
      unsigned off = (unsigned)((d + j)*W_STR + o)*2;
      *(__half2*)(smem + W_BHI + off) = hh;
    }
  }
  __syncthreads();

  float acc[2][4][4];
  #pragma unroll
  for (int i = 0; i < 2; i++)
    #pragma unroll
    for (int j = 0; j < 4; j++)
      #pragma unroll
      for (int q = 0; q < 4; q++) acc[i][j][q] = 0.f;

  #pragma unroll
  for (int ks = 0; ks < 16; ks++){
    const int k = ks*16;
    unsigned ah[2][4], al[2][4], bh[2][4];
    #pragma unroll
    for (int mi = 0; mi < 2; mi++){
      unsigned aoff =
        (unsigned)((wm*32 + mi*16 + (lane & 15))*W_STR + k + ((lane >> 4) << 3))*2;
      ldsm4(ah[mi], sbase + W_AHI + aoff);
      ldsm4(al[mi], sbase + W_ALO + aoff);
    }
    #pragma unroll
    for (int ng = 0; ng < 2; ng++){
      unsigned boff =
        (unsigned)((wn*32 + ng*16 + (lane & 7) + ((lane >> 4) << 3))*W_STR + k + (((lane >> 3) & 1) << 3))*2;
      ldsm4(bh[ng], sbase + W_BHI + boff);
    }
    #pragma unroll
    for (int mi = 0; mi < 2; mi++)
      #pragma unroll
      for (int ng = 0; ng < 2; ng++){
        mma16816(acc[mi][2*ng+0], ah[mi], &bh[ng][0]);
        mma16816(acc[mi][2*ng+1], ah[mi], &bh[ng][2]);
        mma16816(acc[mi][2*ng+0], al[mi], &bh[ng][0]);
        mma16816(acc[mi][2*ng+1], al[mi], &bh[ng][2]);
      }
  }

  #pragma unroll
  for (int mi = 0; mi < 2; mi++){
    int row = n0 + wm*32 + mi*16 + (lane >> 2);
    #pragma unroll
    for (int nj = 0; nj < 4; nj++){
      int col = r*64 + wn*32 + nj*8 + (lane & 3)*2;
      __half2 v01 = __floats2half2_rn(acc[mi][nj][0], acc[mi][nj][1]);
      __half2 v23 = __floats2half2_rn(acc[mi][nj][2], acc[mi][nj][3]);
      *(__half2*)(g_wt + (size_t)row*KAUG + col) = v01;
      *(__half2*)(g_wt + (size_t)(row + 8)*KAUG + col) = v23;
    }
  }
}

// ================= fused GEMM + attention + output projection =================
// Tile 64(M=edges) x 256(N), K-chunk 64, 3-stage cp.async, 512 threads, grid 128.
// Stage-(r+2) load/build issued AFTER stage-r MMAs.
#define A_T   9216              // 64 * 72 * 2
#define B_T   36864             // 256 * 72 * 2
#define B_OFF (3*A_T)           // 27648
#define H_OFF (B_OFF + 3*B_T)   // 138240
#define G_SMT (H_OFF + 64*65*4) // 154880
#define SSTR  72
#define SACS  264               // epilogue accum stride (floats)

__global__ void __launch_bounds__(512, 1) k_gemm_attn(
    const int* __restrict__ nidx, const float* __restrict__ Wout,
    float* __restrict__ out){
  extern __shared__ __align__(16) char smem[];
  const unsigned sbase = (unsigned)__cvta_generic_to_shared(smem);
  float* sHdd = (float*)(smem + H_OFF);

  const int tid  = threadIdx.x;
  const int lane = tid & 31;
  const int wid  = tid >> 5;
  const int wm   = wid & 1;         // 2 m-warps, 32 rows each
  const int wn   = wid >> 1;        // 8 n-warps, 32 cols each
  const int m0   = blockIdx.x * 64;

  // stage hdd [64][65]
  #pragma unroll
  for (int i = 0; i < 8; i++){
    int idx = tid + i*512;
    int row = idx >> 6, c = idx & 63;
    sHdd[row*65 + c] = g_hdd[(size_t)(m0+row)*64 + c];
  }
  // per-thread xe slice (gather fused): row = tid>>3, 8 cols
  const int arow = tid >> 3;
  const int qc   = (tid & 7) * 8;
  float xev[8];
  {
    int e    = m0 + arow;
    int node = e >> 4;
    int b    = node >> 8;
    int nb   = b*NN + nidx[e];
    const float* pj = g_xj + (size_t)nb*ND + qc;
    const float* pi = g_xi + (size_t)node*ND + qc;
    #pragma unroll
    for (int j = 0; j < 8; j++) xev[j] = pj[j] + pi[j];
  }
  __syncthreads();

  auto loadB = [&](int s, int kbase){
    unsigned sm0 = sbase + B_OFF + (unsigned)s*B_T;
    #pragma unroll
    for (int i = 0; i < 4; i++){
      int q = tid + i*512;
      int row = q >> 3, w8 = q & 7;
      cpasync16(sm0 + (unsigned)(row*SSTR + w8*8)*2,
                g_wt + (size_t)row*KAUG + kbase + w8*8);
    }
  };
  auto buildA = [&](int s, int r){
    float h = (r < 64) ? sHdd[arow*65 + r] : 1.0f;
    char* aT = smem + s*A_T;
    unsigned off = (unsigned)(arow*SSTR + qc)*2;
    uint4 hv;
    unsigned* hp = (unsigned*)&hv;
    #pragma unroll
    for (int m = 0; m < 4; m++){
      __half2 hh = __floats2half2_rn(h * xev[2*m], h * xev[2*m + 1]);
      hp[m] = *(unsigned*)&hh;
    }
    *(uint4*)(aT + off) = hv;
  };

  float acc[2][4][4];
  #pragma unroll
  for (int i = 0; i < 2; i++)
    #pragma unroll
    for (int j = 0; j < 4; j++)
      #pragma unroll
      for (int q = 0; q < 4; q++) acc[i][j][q] = 0.f;

  // prologue: stages 0 and 1
  loadB(0, 0);
  asm volatile("cp.async.commit_group;" ::: "memory");
  buildA(0, 0);
  loadB(1, 64);
  asm volatile("cp.async.commit_group;" ::: "memory");
  buildA(1, 1);

  for (int r = 0; r <= 64; r++){
    const int s = r % 3;
    asm volatile("cp.async.wait_group 1;" ::: "memory");
    __syncthreads();

    const unsigned aB = sbase + (unsigned)s*A_T;
    const unsigned bB = sbase + B_OFF + (unsigned)s*B_T;
    #pragma unroll
    for (int ks = 0; ks < 4; ks++){
      const int kk = ks*16;
      unsigned a[2][4], b[2][4];
      #pragma unroll
      for (int mi = 0; mi < 2; mi++){
        unsigned aoff =
          (unsigned)((wm*32 + mi*16 + (lane & 15))*SSTR + kk + ((lane >> 4) << 3))*2;
        ldsm4(a[mi], aB + aoff);
      }
      #pragma unroll
      for (int ng = 0; ng < 2; ng++){
        int nb = wn*32 + ng*16;
        unsigned addr = bB +
          (unsigned)((nb + (lane & 7) + ((lane >> 4) << 3))*SSTR + kk + (((lane >> 3) & 1) << 3))*2;
        ldsm4(b[ng], addr);
      }
      #pragma unroll
      for (int mi = 0; mi < 2; mi++)
        #pragma unroll
        for (int ng = 0; ng < 2; ng++){
          mma16816(acc[mi][2*ng+0], a[mi], &b[ng][0]);
          mma16816(acc[mi][2*ng+1], a[mi], &b[ng][2]);
        }
    }

    // stage r+2 load/build AFTER this stage's MMAs
    const int rn = r + 2;
    if (rn <= 64){
      const int s2 = rn % 3;
      loadB(s2, (rn < 64) ? rn*64 : 4096);
      asm volatile("cp.async.commit_group;" ::: "memory");
      buildA(s2, rn);
    } else {
      asm volatile("cp.async.commit_group;" ::: "memory");
    }
  }

  // ================= fused epilogue: attention + Wout projection =================
  __syncthreads();            // all warps done with tiles; reuse smem
  float* sacc  = (float*)smem;                 // [64][SACS]
  float* s_out = (float*)smem + 64*SACS;       // [4][128]
  float* sWout = s_out + 4*NHID;               // [128][64]

  // store accumulators to SMEM
  #pragma unroll
  for (int mi = 0; mi < 2; mi++){
    int row = wm*32 + mi*16 + (lane >> 2);
    #pragma unroll
    for (int nj = 0; nj < 4; nj++){
      int col = wn*32 + nj*8 + (lane & 3)*2;
      *(float2*)&sacc[row*SACS + col] = make_float2(acc[mi][nj][0], acc[mi][nj][1]);
      *(float2*)&sacc[(row + 8)*SACS + col] = make_float2(acc[mi][nj][2], acc[mi][nj][3]);
    }
  }
  // stage Wout (128x64 f32 = 2048 float4)
  #pragma unroll
  for (int i = 0; i < 4; i++)
    ((float4*)sWout)[tid + i*512] = ((const float4*)Wout)[tid + i*512];
  __syncthreads();

  // attention: 4 nodes x 128 threads; per-head (32-lane) shuffle reduce
  const int nodeL = tid >> 7;
  const int st    = tid & 127;
  const int gnode = blockIdx.x*4 + nodeL;
  {
    float qv = g_q[gnode*NHID + st];
    float sim[NK];
    #pragma unroll
    for (int j = 0; j < NK; j++){
      float dff = qv - sacc[(nodeL*NK + j)*SACS + st] + 1e-6f;
      sim[j] = dff * dff;
    }
    #pragma unroll
    for (int j = 0; j < NK; j++){
      float s = sim[j];
      #pragma unroll
      for (int o = 16; o; o >>= 1) s += __shfl_xor_sync(0xffffffffu, s, o);
      float m = g_maskf[gnode*NK + j];
      sim[j] = (m != 0.f) ? (-sqrtf(s) * 0.17677669529663687f) : -3.402823466e38f;
    }
    float mx = sim[0];
    #pragma unroll
    for (int j = 1; j < NK; j++) mx = fmaxf(mx, sim[j]);
    float p[NK], den = 0.f;
    #pragma unroll
    for (int j = 0; j < NK; j++){ p[j] = expf(sim[j] - mx); den += p[j]; }
    float o = 0.f;
    #pragma unroll
    for (int j = 0; j < NK; j++)
      o = fmaf(p[j], sacc[(nodeL*NK + j)*SACS + NHID + st], o);
    s_out[nodeL*NHID + st] = o / den;
  }
  __syncthreads();
  if (st < ND){
    float a = 0.f;
    #pragma unroll
    for (int c = 0; c < NHID; c++) a = fmaf(s_out[nodeL*NHID + c], sWout[c*ND + st], a);
    out[gnode*ND + st] = a;
  }
}

// ---------------- launch ----------------
extern "C" void kernel_launch(void* const* d_in, const int* in_sizes, int n_in,
                              void* d_out, int out_size){
  const float* features = (const float*)d_in[0];
  const int*   nidx     = (const int*)  d_in[1];
  const unsigned char* mask = (const unsigned char*)d_in[2];
  const float* rel      = (const float*)d_in[3];
  const float* nscale   = (const float*)d_in[4];
  const float* Wq       = (const float*)d_in[5];
  const float* Wxi      = (const float*)d_in[6];
  const float* Wxj      = (const float*)d_in[7];
  const float* rp_W1    = (const float*)d_in[8];
  const float* rp_b1    = (const float*)d_in[9];
  const float* rp_g1    = (const float*)d_in[10];
  const float* rp_W2    = (const float*)d_in[11];
  const float* rp_b2    = (const float*)d_in[12];
  const float* rp_g2    = (const float*)d_in[13];
  const float* rp_W3    = (const float*)d_in[14];
  const float* rp_b3    = (const float*)d_in[15];
  const float* Wkv      = (const float*)d_in[16];
  const float* Wout     = (const float*)d_in[17];
  float* out = (float*)d_out;

  cudaFuncSetAttribute(k_wcomb,     cudaFuncAttributeMaxDynamicSharedMemorySize, W_SMT);
  cudaFuncSetAttribute(k_gemm_attn, cudaFuncAttributeMaxDynamicSharedMemorySize, G_SMT);

  k_pre_radial <<<512 + NODES + 1, 256>>>(features, nscale, Wq, Wxi, Wxj, mask,
                                          rel, rp_W1, rp_b1, rp_g1, rp_W2, rp_b2, rp_g2);
  k_wcomb     <<<dim3(65, 2), 256, W_SMT>>>(rp_W3, rp_b3, Wkv);
  k_gemm_attn <<<128, 512, G_SMT>>>(nidx, Wout, out);
}

// round 16
// speedup vs baseline: 1.4729x; 1.4729x over previous
#include <cuda_runtime.h>
#include <cuda_fp16.h>
#include <math.h>
#include <stdint.h>

// Shapes (fixed)
#define NB    2
#define NN    256
#define NK    16
#define ND    64
#define NHID  128
#define NKVD  256
#define NODES 512
#define EDGES 8192
#define KAUG  4160          // 64*64 + 64 bias rows

// ---------------- scratch ----------------
__device__ float g_q[NODES*NHID];
__device__ float g_xi[NODES*ND];
__device__ float g_xj[NODES*ND];
__device__ float g_hdd[EDGES*64];
__device__ __align__(128) __half g_wt[NKVD*KAUG];   // [o2][kaug], fp16
__device__ float g_maskf[EDGES];

__device__ __forceinline__ float silu(float x){ return x / (1.f + __expf(-x)); }

// ---------------- fused pre (prenorm+proj) + radial MLP + mask detect ----------------
// grid: [0,512) radial (16 edges each), [512, 512+NODES) pre, 512+NODES mask
__global__ void __launch_bounds__(256) k_pre_radial(
    const float* __restrict__ f, const float* __restrict__ nscale,
    const float* __restrict__ Wq, const float* __restrict__ Wxi,
    const float* __restrict__ Wxj, const unsigned char* __restrict__ mraw,
    const float* __restrict__ rel,
    const float* __restrict__ W1, const float* __restrict__ b1,
    const float* __restrict__ g1, const float* __restrict__ W2,
    const float* __restrict__ b2, const float* __restrict__ g2){
  int t = threadIdx.x;

  if (blockIdx.x < 512){
    // ---- radial: warp handles 2 edges ----
    __shared__ float sW2[64][64];
    __shared__ float shh[16][64];
    int w = t >> 5, lane = t & 31;
    #pragma unroll
    for (int i = 0; i < 4; i++)
      ((float4*)sW2)[t + i*256] = ((const float4*)W2)[t + i*256];
    __syncthreads();
    int c0 = lane, c1 = lane + 32;
    float w1c0 = W1[c0], w1c1 = W1[c1];
    float b1c0 = b1[c0], b1c1 = b1[c1];
    float g1c0 = g1[c0], g1c1 = g1[c1];
    float b2c0 = b2[c0], b2c1 = b2[c1];
    float g2c0 = g2[c0], g2c1 = g2[c1];
    #pragma unroll
    for (int ed = 0; ed < 2; ed++){
      int sl = w*2 + ed;
      int e  = blockIdx.x*16 + sl;
      float r = rel[e];
      float h0 = silu(fmaf(r, w1c0, b1c0));
      float h1 = silu(fmaf(r, w1c1, b1c1));
      float s = h0 + h1;
      #pragma unroll
      for (int o = 16; o; o >>= 1) s += __shfl_xor_sync(0xffffffffu, s, o);
      float mu = s * (1.f/64.f);
      float d0 = h0 - mu, d1 = h1 - mu;
      float v = d0*d0 + d1*d1;
      #pragma unroll
      for (int o = 16; o; o >>= 1) v += __shfl_xor_sync(0xffffffffu, v, o);
      float rs = rsqrtf(v*(1.f/64.f) + 1e-5f);
      h0 = d0*rs*g1c0;
      h1 = d1*rs*g1c1;
      shh[sl][c0] = h0;
      shh[sl][c1] = h1;
      __syncwarp();
      float a0 = b2c0, a1 = b2c1;
      #pragma unroll
      for (int i = 0; i < 64; i++){
        float hv = shh[sl][i];
        a0 = fmaf(hv, sW2[i][c0], a0);
        a1 = fmaf(hv, sW2[i][c1], a1);
      }
      a0 = silu(a0); a1 = silu(a1);
      s = a0 + a1;
      #pragma unroll
      for (int o = 16; o; o >>= 1) s += __shfl_xor_sync(0xffffffffu, s, o);
      mu = s * (1.f/64.f);
      d0 = a0 - mu; d1 = a1 - mu;
      v = d0*d0 + d1*d1;
      #pragma unroll
      for (int o = 16; o; o >>= 1) v += __shfl_xor_sync(0xffffffffu, v, o);
      rs = rsqrtf(v*(1.f/64.f) + 1e-5f);
      g_hdd[e*64 + c0] = d0*rs*g2c0;
      g_hdd[e*64 + c1] = d1*rs*g2c1;
    }
    return;
  }

  if (blockIdx.x == 512 + NODES){
    // ---- mask dtype detection + expansion ----
    __shared__ int flags[2];
    if (t < 2) flags[t] = 0;
    __syncthreads();
    int f3 = 0, fn = 0;
    for (int i = t; i < EDGES; i += 256){
      unsigned char bb = mraw[i];
      if (bb == 0x3fu) f3 = 1;
      if ((i & 3) && bb) fn = 1;
    }
    if (f3) atomicOr(&flags[0], 1);
    if (fn) atomicOr(&flags[1], 1);
    __syncthreads();
    int mode = flags[0] ? 2 : (flags[1] ? 0 : 1);
    for (int i = t; i < EDGES; i += 256){
      float m;
      if (mode == 2)      m = (((const float*)mraw)[i] != 0.f) ? 1.f : 0.f;
      else if (mode == 1) m = (((const int*)  mraw)[i] != 0  ) ? 1.f : 0.f;
      else                m = (mraw[i] != 0) ? 1.f : 0.f;
      g_maskf[i] = m;
    }
    return;
  }

  // ---- pre: prenorm + projections ----
  __shared__ float sv[ND];
  __shared__ float sx[ND];
  int node = blockIdx.x - 512;
  if (t < ND) sv[t] = f[node*ND + t];
  __syncthreads();
  float ss = 0.f;
  #pragma unroll
  for (int d = 0; d < ND; d++) ss = fmaf(sv[d], sv[d], ss);
  float den = fmaxf(sqrtf(ss) * 0.125f, 1e-12f);
  if (t < ND) sx[t] = sv[t] / den * nscale[t];
  __syncthreads();
  if (t < NHID){
    float a = 0.f;
    #pragma unroll
    for (int d = 0; d < ND; d++) a = fmaf(sx[d], Wq[d*NHID + t], a);
    g_q[node*NHID + t] = a;
  } else if (t < NHID + ND){
    int c = t - NHID; float a = 0.f;
    #pragma unroll
    for (int d = 0; d < ND; d++) a = fmaf(sx[d], Wxi[d*ND + c], a);
    g_xi[node*ND + c] = a;
  } else {
    int c = t - NHID - ND; float a = 0.f;
    #pragma unroll
    for (int d = 0; d < ND; d++) a = fmaf(sx[d], Wxj[d*ND + c], a);
    g_xj[node*ND + c] = a;
  }
}

// ---------------- shared MMA helpers ----------------
static __device__ __forceinline__ void cpasync16(unsigned sm, const void* g){
  asm volatile("cp.async.cg.shared.global [%0], [%1], 16;" :: "r"(sm), "l"(g));
}
static __device__ __forceinline__ void ldsm4(unsigned* r, unsigned addr){
  asm volatile("ldmatrix.sync.aligned.m8n8.x4.shared.b16 {%0,%1,%2,%3}, [%4];"
               : "=r"(r[0]), "=r"(r[1]), "=r"(r[2]), "=r"(r[3]) : "r"(addr));
}
static __device__ __forceinline__ void mma16816(float* c, const unsigned* a, const unsigned* b){
  asm volatile(
    "mma.sync.aligned.m16n8k16.row.col.f32.f16.f16.f32 "
    "{%0,%1,%2,%3}, {%4,%5,%6,%7}, {%8,%9}, {%0,%1,%2,%3};"
    : "+f"(c[0]), "+f"(c[1]), "+f"(c[2]), "+f"(c[3])
    : "r"(a[0]), "r"(a[1]), "r"(a[2]), "r"(a[3]), "r"(b[0]), "r"(b[1]));
}

// ================= wcomb via mma.sync (hi/lo both operands, 3 products) =================
#define W_STR 264
#define W_AHI 0
#define W_ALO 67584
#define W_BHI 135168
#define W_BLO 168960
#define W_SMT 202752

__global__ void __launch_bounds__(256, 1) k_wcomb(
    const float* __restrict__ W3, const float* __restrict__ b3,
    const float* __restrict__ Wkv){
  extern __shared__ __align__(16) char smem[];
  const unsigned sbase = (unsigned)__cvta_generic_to_shared(smem);
  const int tid  = threadIdx.x;
  const int lane = tid & 31;
  const int wid  = tid >> 5;
  const int wm   = wid & 3;
  const int wn   = wid >> 2;
  const int r    = blockIdx.x;      // 0..64 (64 = bias block)
  const int n0   = blockIdx.y * 128;
  const float* srcB = (r < 64) ? (W3 + (size_t)r*16384) : b3;

  #pragma unroll
  for (int i = 0; i < 16; i++){
    int u = tid + i*256;
    int opair = u >> 5, f4 = u & 31;
    int o = opair*2, n = f4*4;
    float4 v0 = *(const float4*)(Wkv + (size_t)o*256 + n0 + n);
    float4 v1 = *(const float4*)(Wkv + (size_t)(o+1)*256 + n0 + n);
    const float* p0 = (const float*)&v0;
    const float* p1 = (const float*)&v1;
    #pragma unroll
    for (int j = 0; j < 4; j++){
      float x0 = p0[j], x1 = p1[j];
      __half h0 = __float2half_rn(x0), h1 = __float2half_rn(x1);
      __half l0 = __float2half_rn(x0 - __half2float(h0));
      __half l1 = __float2half_rn(x1 - __half2float(h1));
      __half2 hh; hh.x = h0; hh.y = h1;
      __half2 ll; ll.x = l0; ll.y = l1;
      unsigned off = (unsigned)((n + j)*W_STR + o)*2;
      *(__half2*)(smem + W_AHI + off) = hh;
      *(__half2*)(smem + W_ALO + off) = ll;
    }
  }
  #pragma unroll
  for (int i = 0; i < 8; i++){
    int u = tid + i*256;
    int opair = u >> 4, f4 = u & 15;
    int o = opair*2, d = f4*4;
    float4 v0 = *(const float4*)(srcB + (size_t)o*64 + d);
    float4 v1 = *(const float4*)(srcB + (size_t)(o+1)*64 + d);
    const float* p0 = (const float*)&v0;
    const float* p1 = (const float*)&v1;
    #pragma unroll
    for (int j = 0; j < 4; j++){
      float x0 = p0[j], x1 = p1[j];
      __half h0 = __float2half_rn(x0), h1 = __float2half_rn(x1);
      __half l0 = __float2half_rn(x0 - __half2float(h0));
      __half l1 = __float2half_rn(x1 - __half2float(h1));
      __half2 hh; hh.x = h0; hh.y = h1;
      __half2 ll; ll.x = l0; ll.y = l1;
      unsigned off = (unsigned)((d + j)*W_STR + o)*2;
      *(__half2*)(smem + W_BHI + off) = hh;
      *(__half2*)(smem + W_BLO + off) = ll;
    }
  }
  __syncthreads();

  float acc[2][4][4];
  #pragma unroll
  for (int i = 0; i < 2; i++)
    #pragma unroll
    for (int j = 0; j < 4; j++)
      #pragma unroll
      for (int q = 0; q < 4; q++) acc[i][j][q] = 0.f;

  #pragma unroll
  for (int ks = 0; ks < 16; ks++){
    const int k = ks*16;
    unsigned ah[2][4], al[2][4], bh[2][4], bl[2][4];
    #pragma unroll
    for (int mi = 0; mi < 2; mi++){
      unsigned aoff =
        (unsigned)((wm*32 + mi*16 + (lane & 15))*W_STR + k + ((lane >> 4) << 3))*2;
      ldsm4(ah[mi], sbase + W_AHI + aoff);
      ldsm4(al[mi], sbase + W_ALO + aoff);
    }
    #pragma unroll
    for (int ng = 0; ng < 2; ng++){
      unsigned boff =
        (unsigned)((wn*32 + ng*16 + (lane & 7) + ((lane >> 4) << 3))*W_STR + k + (((lane >> 3) & 1) << 3))*2;
      ldsm4(bh[ng], sbase + W_BHI + boff);
      ldsm4(bl[ng], sbase + W_BLO + boff);
    }
    #pragma unroll
    for (int mi = 0; mi < 2; mi++)
      #pragma unroll
      for (int ng = 0; ng < 2; ng++){
        mma16816(acc[mi][2*ng+0], ah[mi], &bh[ng][0]);
        mma16816(acc[mi][2*ng+1], ah[mi], &bh[ng][2]);
        mma16816(acc[mi][2*ng+0], ah[mi], &bl[ng][0]);
        mma16816(acc[mi][2*ng+1], ah[mi], &bl[ng][2]);
        mma16816(acc[mi][2*ng+0], al[mi], &bh[ng][0]);
        mma16816(acc[mi][2*ng+1], al[mi], &bh[ng][2]);
      }
  }

  #pragma unroll
  for (int mi = 0; mi < 2; mi++){
    int row = n0 + wm*32 + mi*16 + (lane >> 2);
    #pragma unroll
    for (int nj = 0; nj < 4; nj++){
      int col = r*64 + wn*32 + nj*8 + (lane & 3)*2;
      __half2 v01 = __floats2half2_rn(acc[mi][nj][0], acc[mi][nj][1]);
      __half2 v23 = __floats2half2_rn(acc[mi][nj][2], acc[mi][nj][3]);
      *(__half2*)(g_wt + (size_t)row*KAUG + col) = v01;
      *(__half2*)(g_wt + (size_t)(row + 8)*KAUG + col) = v23;
    }
  }
}

// ================= fused GEMM + attention + output projection =================
// Tile 64(M=edges) x 256(N), K-chunk 64, 3-stage cp.async, 512 threads, grid 128.
// Stage-(r+2) load/build issued AFTER stage-r MMAs (tensor pipe starts right at sync).
#define A_T   9216              // 64 * 72 * 2
#define B_T   36864             // 256 * 72 * 2
#define B_OFF (3*A_T)           // 27648
#define H_OFF (B_OFF + 3*B_T)   // 138240
#define G_SMT (H_OFF + 64*65*4) // 154880
#define SSTR  72
#define SACS  264               // epilogue accum stride (floats)

__global__ void __launch_bounds__(512, 1) k_gemm_attn(
    const int* __restrict__ nidx, const float* __restrict__ Wout,
    float* __restrict__ out){
  extern __shared__ __align__(16) char smem[];
  const unsigned sbase = (unsigned)__cvta_generic_to_shared(smem);
  float* sHdd = (float*)(smem + H_OFF);

  const int tid  = threadIdx.x;
  const int lane = tid & 31;
  const int wid  = tid >> 5;
  const int wm   = wid & 1;         // 2 m-warps, 32 rows each
  const int wn   = wid >> 1;        // 8 n-warps, 32 cols each
  const int m0   = blockIdx.x * 64;

  // stage hdd [64][65]
  #pragma unroll
  for (int i = 0; i < 8; i++){
    int idx = tid + i*512;
    int row = idx >> 6, c = idx & 63;
    sHdd[row*65 + c] = g_hdd[(size_t)(m0+row)*64 + c];
  }
  // per-thread xe slice (gather fused): row = tid>>3, 8 cols
  const int arow = tid >> 3;
  const int qc   = (tid & 7) * 8;
  float xev[8];
  {
    int e    = m0 + arow;
    int node = e >> 4;
    int b    = node >> 8;
    int nb   = b*NN + nidx[e];
    const float* pj = g_xj + (size_t)nb*ND + qc;
    const float* pi = g_xi + (size_t)node*ND + qc;
    #pragma unroll
    for (int j = 0; j < 8; j++) xev[j] = pj[j] + pi[j];
  }
  __syncthreads();

  auto loadB = [&](int s, int kbase){
    unsigned sm0 = sbase + B_OFF + (unsigned)s*B_T;
    #pragma unroll
    for (int i = 0; i < 4; i++){
      int q = tid + i*512;
      int row = q >> 3, w8 = q & 7;
      cpasync16(sm0 + (unsigned)(row*SSTR + w8*8)*2,
                g_wt + (size_t)row*KAUG + kbase + w8*8);
    }
  };
  auto buildA = [&](int s, int r){
    float h = (r < 64) ? sHdd[arow*65 + r] : 1.0f;
    char* aT = smem + s*A_T;
    unsigned off = (unsigned)(arow*SSTR + qc)*2;
    uint4 hv;
    unsigned* hp = (unsigned*)&hv;
    #pragma unroll
    for (int m = 0; m < 4; m++){
      __half2 hh = __floats2half2_rn(h * xev[2*m], h * xev[2*m + 1]);
      hp[m] = *(unsigned*)&hh;
    }
    *(uint4*)(aT + off) = hv;
  };

  float acc[2][4][4];
  #pragma unroll
  for (int i = 0; i < 2; i++)
    #pragma unroll
    for (int j = 0; j < 4; j++)
      #pragma unroll
      for (int q = 0; q < 4; q++) acc[i][j][q] = 0.f;

  // prologue: stages 0 and 1
  loadB(0, 0);
  asm volatile("cp.async.commit_group;" ::: "memory");
  buildA(0, 0);
  loadB(1, 64);
  asm volatile("cp.async.commit_group;" ::: "memory");
  buildA(1, 1);

  for (int r = 0; r <= 64; r++){
    const int s = r % 3;
    asm volatile("cp.async.wait_group 1;" ::: "memory");
    __syncthreads();

    const unsigned aB = sbase + (unsigned)s*A_T;
    const unsigned bB = sbase + B_OFF + (unsigned)s*B_T;
    #pragma unroll
    for (int ks = 0; ks < 4; ks++){
      const int kk = ks*16;
      unsigned a[2][4], b[2][4];
      #pragma unroll
      for (int mi = 0; mi < 2; mi++){
        unsigned aoff =
          (unsigned)((wm*32 + mi*16 + (lane & 15))*SSTR + kk + ((lane >> 4) << 3))*2;
        ldsm4(a[mi], aB + aoff);
      }
      #pragma unroll
      for (int ng = 0; ng < 2; ng++){
        int nb = wn*32 + ng*16;
        unsigned addr = bB +
          (unsigned)((nb + (lane & 7) + ((lane >> 4) << 3))*SSTR + kk + (((lane >> 3) & 1) << 3))*2;
        ldsm4(b[ng], addr);
      }
      #pragma unroll
      for (int mi = 0; mi < 2; mi++)
        #pragma unroll
        for (int ng = 0; ng < 2; ng++){
          mma16816(acc[mi][2*ng+0], a[mi], &b[ng][0]);
          mma16816(acc[mi][2*ng+1], a[mi], &b[ng][2]);
        }
    }

    // stage r+2 load/build AFTER this stage's MMAs
    const int rn = r + 2;
    if (rn <= 64){
      const int s2 = rn % 3;
      loadB(s2, (rn < 64) ? rn*64 : 4096);
      asm volatile("cp.async.commit_group;" ::: "memory");
      buildA(s2, rn);
    } else {
      asm volatile("cp.async.commit_group;" ::: "memory");
    }
  }

  // ================= fused epilogue: attention + Wout projection =================
  __syncthreads();            // all warps done with tiles; reuse smem
  float* sacc  = (float*)smem;                 // [64][SACS]
  float* s_out = (float*)smem + 64*SACS;       // [4][128]
  float* sWout = s_out + 4*NHID;               // [128][64]

  // store accumulators to SMEM
  #pragma unroll
  for (int mi = 0; mi < 2; mi++){
    int row = wm*32 + mi*16 + (lane >> 2);
    #pragma unroll
    for (int nj = 0; nj < 4; nj++){
      int col = wn*32 + nj*8 + (lane & 3)*2;
      *(float2*)&sacc[row*SACS + col] = make_float2(acc[mi][nj][0], acc[mi][nj][1]);
      *(float2*)&sacc[(row + 8)*SACS + col] = make_float2(acc[mi][nj][2], acc[mi][nj][3]);
    }
  }
  // stage Wout (128x64 f32 = 2048 float4)
  #pragma unroll
  for (int i = 0; i < 4; i++)
    ((float4*)sWout)[tid + i*512] = ((const float4*)Wout)[tid + i*512];
  __syncthreads();

  // attention: 4 nodes x 128 threads; per-head (32-lane) shuffle reduce
  const int nodeL = tid >> 7;
  const int st    = tid & 127;
  const int gnode = blockIdx.x*4 + nodeL;
  {
    float qv = g_q[gnode*NHID + st];
    float sim[NK];
    #pragma unroll
    for (int j = 0; j < NK; j++){
      float dff = qv - sacc[(nodeL*NK + j)*SACS + st] + 1e-6f;
      sim[j] = dff * dff;
    }
    #pragma unroll
    for (int j = 0; j < NK; j++){
      float s = sim[j];
      #pragma unroll
      for (int o = 16; o; o >>= 1) s += __shfl_xor_sync(0xffffffffu, s, o);
      float m = g_maskf[gnode*NK + j];
      sim[j] = (m != 0.f) ? (-sqrtf(s) * 0.17677669529663687f) : -3.402823466e38f;
    }
    float mx = sim[0];
    #pragma unroll
    for (int j = 1; j < NK; j++) mx = fmaxf(mx, sim[j]);
    float p[NK], den = 0.f;
    #pragma unroll
    for (int j = 0; j < NK; j++){ p[j] = expf(sim[j] - mx); den += p[j]; }
    float o = 0.f;
    #pragma unroll
    for (int j = 0; j < NK; j++)
      o = fmaf(p[j], sacc[(nodeL*NK + j)*SACS + NHID + st], o);
    s_out[nodeL*NHID + st] = o / den;
  }
  __syncthreads();
  if (st < ND){
    float a = 0.f;
    #pragma unroll
    for (int c = 0; c < NHID; c++) a = fmaf(s_out[nodeL*NHID + c], sWout[c*ND + st], a);
    out[gnode*ND + st] = a;
  }
}

// ---------------- launch ----------------
extern "C" void kernel_launch(void* const* d_in, const int* in_sizes, int n_in,
                              void* d_out, int out_size){
  const float* features = (const float*)d_in[0];
  const int*   nidx     = (const int*)  d_in[1];
  const unsigned char* mask = (const unsigned char*)d_in[2];
  const float* rel      = (const float*)d_in[3];
  const float* nscale   = (const float*)d_in[4];
  const float* Wq       = (const float*)d_in[5];
  const float* Wxi      = (const float*)d_in[6];
  const float* Wxj      = (const float*)d_in[7];
  const float* rp_W1    = (const float*)d_in[8];
  const float* rp_b1    = (const float*)d_in[9];
  const float* rp_g1    = (const float*)d_in[10];
  const float* rp_W2    = (const float*)d_in[11];
  const float* rp_b2    = (const float*)d_in[12];
  const float* rp_g2    = (const float*)d_in[13];
  const float* rp_W3    = (const float*)d_in[14];
  const float* rp_b3    = (const float*)d_in[15];
  const float* Wkv      = (const float*)d_in[16];
  const float* Wout     = (const float*)d_in[17];
  float* out = (float*)d_out;

  cudaFuncSetAttribute(k_wcomb,     cudaFuncAttributeMaxDynamicSharedMemorySize, W_SMT);
  cudaFuncSetAttribute(k_gemm_attn, cudaFuncAttributeMaxDynamicSharedMemorySize, G_SMT);

  k_pre_radial <<<512 + NODES + 1, 256>>>(features, nscale, Wq, Wxi, Wxj, mask,
                                          rel, rp_W1, rp_b1, rp_g1, rp_W2, rp_b2, rp_g2);
  k_wcomb     <<<dim3(65, 2), 256, W_SMT>>>(rp_W3, rp_b3, Wkv);
  k_gemm_attn <<<128, 512, G_SMT>>>(nidx, Wout, out);
}